// round 10
// baseline (speedup 1.0000x reference)
#include <cuda_runtime.h>
#include <cuda_bf16.h>

// VectorQuantizer forward, single fused kernel:
//   q    = codebook[categories]   (row gather, 512x768 codebook -> L2 resident)
//   out  = q
//   loss = 1.25 * mean((q - inputs)^2)
//
// Loss reduction: one packed 64-bit integer atomicAdd per block.
//   bits [0:52)  : fixed-point (2^20) partial sum accumulator
//   bits [52:64) : block-arrival count
// Integer adds are associative -> bit-deterministic; the atomicAdd return
// value lets the last block detect completion AND recover the full sum
// (no fence, no second pass, no second kernel).
//
// Config notes (GB300, measured):
//  - 256-thread blocks: 8 blk/SM x 8 warps = 64/64 warps (192-thr shape capped
//    at 60/64). DRAM-latency-bound streamer -> warps convert to bandwidth.
//  - Flat indexing: block owns 16 rows = 3072 contiguous float4; in/out stay
//    fully coalesced; cb gather uses row = idx/192 (mul-shift) + shared scat.
//  - No __ldcs/__stcs (measured harmful R5/R7). unroll 4 (8 blew regs, R4).
//
// inputs:     [65536, 768] f32
// categories: [65536]      int32
// codebook:   [512, 768]   f32
// out:        65536*768 f32 quantized_st, then 1 f32 loss (if out_size permits)

#define VQ_BS    65536
#define VQ_D4    192                  // float4s per row
#define VQ_ROWS  16                   // rows per block
#define VQ_TPB   256                  // threads per block
#define VQ_F4PB  (VQ_ROWS * VQ_D4)    // 3072 float4s per block
#define VQ_ITERS (VQ_F4PB / VQ_TPB)   // 12 per thread
#define VQ_NBLK  (VQ_BS / VQ_ROWS)    // 4096 blocks

#define VQ_CNT_SHIFT 52
#define VQ_FX_SCALE  1048576.0        // 2^20

__device__ unsigned long long g_vq_acc = 0ULL;   // reset by last block -> replay-idempotent

__global__ __launch_bounds__(VQ_TPB, 8) void vq_kernel(
    const float4* __restrict__ in,
    const int* __restrict__ cat,
    const float4* __restrict__ cb,
    float4* __restrict__ out,
    float* __restrict__ loss_out,
    int write_loss)
{
    const int t = threadIdx.x;                       // 0..255
    const int row_base = blockIdx.x * VQ_ROWS;
    const size_t blk_f4 = (size_t)blockIdx.x * VQ_F4PB;

    // Hoist index gather once per block.
    __shared__ int scat[VQ_ROWS];
    if (t < VQ_ROWS) scat[t] = cat[row_base + t] & 511;   // mask: no-op on valid data
    __syncthreads();

    float s = 0.0f;

    #pragma unroll 4
    for (int k = 0; k < VQ_ITERS; k++) {
        const int idx = t + k * VQ_TPB;              // 0..3071 within block tile
        const int row = idx / VQ_D4;                 // const-div -> mul/shift
        const int col = idx - row * VQ_D4;
        const size_t gib = blk_f4 + idx;             // flat, fully coalesced
        float4 a = in[gib];
        float4 q = cb[(size_t)scat[row] * VQ_D4 + col];
        out[gib] = q;
        float dx = q.x - a.x;
        float dy = q.y - a.y;
        float dz = q.z - a.z;
        float dw = q.w - a.w;
        s += dx*dx + dy*dy + dz*dz + dw*dw;
    }

    // block reduction: 8 warps of 32
    #pragma unroll
    for (int o = 16; o > 0; o >>= 1)
        s += __shfl_down_sync(0xffffffffu, s, o);

    __shared__ float ws[8];
    if ((t & 31) == 0) ws[t >> 5] = s;
    __syncthreads();

    if (t == 0) {
        float tot = ws[0] + ws[1] + ws[2] + ws[3] + ws[4] + ws[5] + ws[6] + ws[7];
        // fixed-point: ~2.4e4 per block -> ~2.5e10 scaled; total ~1.05e14 < 2^52
        unsigned long long fx = (unsigned long long)((double)tot * VQ_FX_SCALE);
        unsigned long long packed = (1ULL << VQ_CNT_SHIFT) + fx;
        unsigned long long old = atomicAdd(&g_vq_acc, packed);

        if ((old >> VQ_CNT_SHIFT) == (unsigned long long)(VQ_NBLK - 1)) {
            unsigned long long full = (old + packed) & ((1ULL << VQ_CNT_SHIFT) - 1ULL);
            if (write_loss) {
                const double inv_n = 1.0 / ((double)VQ_BS * 768.0);
                double mse = ((double)full / VQ_FX_SCALE) * inv_n;
                // loss = (CODEBOOK_COST + COMMITMENT_COST) * mse = 1.25 * mse
                loss_out[(size_t)VQ_BS * 768] = (float)(1.25 * mse);
            }
            g_vq_acc = 0ULL;   // reset for next graph replay (no other block alive)
        }
    }
}

extern "C" void kernel_launch(void* const* d_in, const int* in_sizes, int n_in,
                              void* d_out, int out_size)
{
    const float4* in  = (const float4*)d_in[0];
    const int*    cat = (const int*)d_in[1];
    const float4* cb  = (const float4*)d_in[2];
    float*        out = (float*)d_out;

    const int write_loss = (out_size > VQ_BS * 768) ? 1 : 0;
    vq_kernel<<<VQ_NBLK, VQ_TPB>>>(in, cat, cb, (float4*)out, out, write_loss);
}

// round 12
// speedup vs baseline: 1.0068x; 1.0068x over previous
#include <cuda_runtime.h>
#include <cuda_bf16.h>

// VectorQuantizer forward, single fused kernel:
//   q    = codebook[categories]   (row gather, 512x768 codebook -> L2 resident)
//   out  = q
//   loss = 1.25 * mean((q - inputs)^2)
//
// Loss reduction: one packed 64-bit integer atomicAdd per block.
//   bits [0:50)  : fixed-point (2^20) partial sum accumulator (max ~1.05e14 < 2^50)
//   bits [50:64) : block-arrival count (14 bits, max 16383 >= 8192 blocks)
// Integer adds are associative -> bit-deterministic; the atomicAdd return
// value lets the last block detect completion AND recover the full sum
// (no fence, no second pass, no second kernel).
//
// Config notes (GB300, measured):
//  - 256-thread blocks: 8 blk/SM x 8 warps = 64/64 warps, regs 32.
//  - ROWS=8 (8192 blocks): 6.9 waves -> tail-wave loss ~0.08 wave (vs 0.54 at
//    ROWS=16/3.46 waves).
//  - unroll 3 caps live float4 regs (full unroll would drop residency).
//  - No __ldcs/__stcs (measured harmful R5/R7).
//  - R11 bug: CNT_SHIFT=52 gave a 12-bit count field (max 4095) -> with 8192
//    blocks the completion test never fired. Fixed with CNT_SHIFT=50.
//
// inputs:     [65536, 768] f32
// categories: [65536]      int32
// codebook:   [512, 768]   f32
// out:        65536*768 f32 quantized_st, then 1 f32 loss (if out_size permits)

#define VQ_BS    65536
#define VQ_D4    192                  // float4s per row
#define VQ_ROWS  8                    // rows per block
#define VQ_TPB   256                  // threads per block
#define VQ_F4PB  (VQ_ROWS * VQ_D4)    // 1536 float4s per block
#define VQ_ITERS (VQ_F4PB / VQ_TPB)   // 6 per thread
#define VQ_NBLK  (VQ_BS / VQ_ROWS)    // 8192 blocks

#define VQ_CNT_SHIFT 50
#define VQ_FX_SCALE  1048576.0        // 2^20

__device__ unsigned long long g_vq_acc = 0ULL;   // reset by last block -> replay-idempotent

__global__ __launch_bounds__(VQ_TPB, 8) void vq_kernel(
    const float4* __restrict__ in,
    const int* __restrict__ cat,
    const float4* __restrict__ cb,
    float4* __restrict__ out,
    float* __restrict__ loss_out,
    int write_loss)
{
    const int t = threadIdx.x;                       // 0..255
    const int row_base = blockIdx.x * VQ_ROWS;
    const size_t blk_f4 = (size_t)blockIdx.x * VQ_F4PB;

    // Hoist index gather once per block.
    __shared__ int scat[VQ_ROWS];
    if (t < VQ_ROWS) scat[t] = cat[row_base + t] & 511;   // mask: no-op on valid data
    __syncthreads();

    float s = 0.0f;

    #pragma unroll 3
    for (int k = 0; k < VQ_ITERS; k++) {
        const int idx = t + k * VQ_TPB;              // 0..1535 within block tile
        const int row = idx / VQ_D4;                 // const-div -> mul/shift
        const int col = idx - row * VQ_D4;
        const size_t gib = blk_f4 + idx;             // flat, fully coalesced
        float4 a = in[gib];
        float4 q = cb[(size_t)scat[row] * VQ_D4 + col];
        out[gib] = q;
        float dx = q.x - a.x;
        float dy = q.y - a.y;
        float dz = q.z - a.z;
        float dw = q.w - a.w;
        s += dx*dx + dy*dy + dz*dz + dw*dw;
    }

    // block reduction: 8 warps of 32
    #pragma unroll
    for (int o = 16; o > 0; o >>= 1)
        s += __shfl_down_sync(0xffffffffu, s, o);

    __shared__ float ws[8];
    if ((t & 31) == 0) ws[t >> 5] = s;
    __syncthreads();

    if (t == 0) {
        float tot = ws[0] + ws[1] + ws[2] + ws[3] + ws[4] + ws[5] + ws[6] + ws[7];
        // fixed-point: ~1.2e4 per block -> ~1.3e10 scaled; total ~1.05e14 < 2^50
        unsigned long long fx = (unsigned long long)((double)tot * VQ_FX_SCALE);
        unsigned long long packed = (1ULL << VQ_CNT_SHIFT) + fx;
        unsigned long long old = atomicAdd(&g_vq_acc, packed);

        if ((old >> VQ_CNT_SHIFT) == (unsigned long long)(VQ_NBLK - 1)) {
            unsigned long long full = (old + packed) & ((1ULL << VQ_CNT_SHIFT) - 1ULL);
            if (write_loss) {
                const double inv_n = 1.0 / ((double)VQ_BS * 768.0);
                double mse = ((double)full / VQ_FX_SCALE) * inv_n;
                // loss = (CODEBOOK_COST + COMMITMENT_COST) * mse = 1.25 * mse
                loss_out[(size_t)VQ_BS * 768] = (float)(1.25 * mse);
            }
            g_vq_acc = 0ULL;   // reset for next graph replay (no other block alive)
        }
    }
}

extern "C" void kernel_launch(void* const* d_in, const int* in_sizes, int n_in,
                              void* d_out, int out_size)
{
    const float4* in  = (const float4*)d_in[0];
    const int*    cat = (const int*)d_in[1];
    const float4* cb  = (const float4*)d_in[2];
    float*        out = (float*)d_out;

    const int write_loss = (out_size > VQ_BS * 768) ? 1 : 0;
    vq_kernel<<<VQ_NBLK, VQ_TPB>>>(in, cat, cb, (float4*)out, out, write_loss);
}